// round 16
// baseline (speedup 1.0000x reference)
#include <cuda_runtime.h>
#include <cuda_fp16.h>
#include <cstdint>

#define BATCH 4
#define SEQ   2048
#define DIM   1024
#define MTOT  (BATCH*SEQ)

// ------------------------- device scratch (no allocs) -----------------------
__device__ __half Xh[MTOT*(size_t)DIM];
__device__ __half Wth[3*(size_t)DIM*DIM];    // [z][n][k], fp16(W) transposed
__device__ __half Qh[MTOT*(size_t)DIM];
__device__ __half Kh[MTOT*(size_t)DIM];
__device__ __half Vth[MTOT*(size_t)DIM];     // [b][d][s]
__device__ __half Ph [(size_t)BATCH*SEQ*SEQ];    // unnormalized exp(scores)
__device__ float  Rsum[MTOT];                    // per-row softmax denominators

// ------------------------------ helpers -------------------------------------
__device__ __forceinline__ uint32_t smem_to_u32(const void* p) {
    uint32_t a;
    asm("{ .reg .u64 t; cvta.to.shared.u64 t, %1; cvt.u32.u64 %0, t; }"
        : "=r"(a) : "l"(p));
    return a;
}
#define SW128(off) ((off) ^ (((off) >> 3) & 0x70))

__device__ __forceinline__ void ldsm_x4(uint32_t* r, uint32_t addr) {
    asm volatile("ldmatrix.sync.aligned.m8n8.x4.shared.b16 {%0,%1,%2,%3}, [%4];"
                 : "=r"(r[0]), "=r"(r[1]), "=r"(r[2]), "=r"(r[3]) : "r"(addr));
}
__device__ __forceinline__ void mma_f16(float* c, const uint32_t* a, const uint32_t* b) {
    asm volatile(
        "mma.sync.aligned.m16n8k16.row.col.f32.f16.f16.f32 "
        "{%0,%1,%2,%3}, {%4,%5,%6,%7}, {%8,%9}, {%0,%1,%2,%3};"
        : "+f"(c[0]), "+f"(c[1]), "+f"(c[2]), "+f"(c[3])
        : "r"(a[0]), "r"(a[1]), "r"(a[2]), "r"(a[3]), "r"(b[0]), "r"(b[1]));
}
__device__ __forceinline__ void cp16(uint32_t smem_dst, const void* gptr) {
    asm volatile("cp.async.cg.shared.global [%0], [%1], 16;"
                 :: "r"(smem_dst), "l"(gptr));
}
__device__ __forceinline__ uint32_t pack_half2(__half a, __half b) {
    __half2 h2 = __halves2half2(a, b);
    return *(uint32_t*)&h2;
}

// ----------------- 1-pass fp16 mainloop, 128m x 128n x 64k, 3 stages ---------
// 8 warps as 2(m) x 4(n): warp tile 64x32. acc[4][4][4].
// Stage (32 KB): Ah[16K] Bh[16K]; rows 128B, SW128. 3 stages = 96 KB -> 2 CTA/SM.
// Prefetch depth 2: prologue issues 0,1; per chunk wait -> sync -> issue(c+2).
#define ST1_BH 16384
#define STAGE1 32768
#define NSTAGE 3
#define GEMM1_SMEM (NSTAGE*STAGE1)   // 98304

__device__ __forceinline__ void gemm_tile_1p(
    const __half* __restrict__ Ahp, size_t lda,
    const __half* __restrict__ Bhp, size_t ldb,
    int kIters, char* smem, float acc[4][4][4])
{
    const int tid = threadIdx.x;
    const int wid = tid >> 5, lane = tid & 31;
    const int wm = (wid & 1) * 64;      // warp m offset
    const int wn = (wid >> 1) * 32;     // warp n offset
    const uint32_t sbase = smem_to_u32(smem);

    const int r8 = tid >> 3, j8 = tid & 7;

    auto issue = [&](int c) {
        const int kc = c * 64;
        const uint32_t st = sbase + (uint32_t)(c % NSTAGE) * STAGE1;
        #pragma unroll
        for (int i = 0; i < 4; i++) {
            const int r = r8 + i * 32;
            const uint32_t off = SW128((uint32_t)(r * 128 + j8 * 16));
            cp16(st + off,          Ahp + (size_t)r * lda + kc + j8 * 8);
            cp16(st + ST1_BH + off, Bhp + (size_t)r * ldb + kc + j8 * 8);
        }
        asm volatile("cp.async.commit_group;" ::: "memory");
    };

    const int a_row = (lane & 15);
    const int a_k8  = ((lane >> 4) & 1) * 8;
    const int b_row = (lane & 7) + ((lane >> 4) & 1) * 8;
    const int b_k8  = ((lane >> 3) & 1) * 8;

    issue(0);
    if (kIters > 1) issue(1);

    for (int c = 0; c < kIters; c++) {
        if (c + 1 < kIters) asm volatile("cp.async.wait_group 1;" ::: "memory");
        else                asm volatile("cp.async.wait_group 0;" ::: "memory");
        __syncthreads();
        if (c + 2 < kIters) issue(c + 2);

        const uint32_t st = sbase + (uint32_t)(c % NSTAGE) * STAGE1;
        #pragma unroll
        for (int ks = 0; ks < 4; ks++) {
            const int kbase = ks * 16;
            uint32_t ah[4][4];
            #pragma unroll
            for (int mi = 0; mi < 4; mi++) {
                const uint32_t off =
                    SW128((uint32_t)((wm + mi * 16 + a_row) * 128 + (kbase + a_k8) * 2));
                ldsm_x4(ah[mi], st + off);
            }
            uint32_t bh[4][2];
            #pragma unroll
            for (int p = 0; p < 2; p++) {
                const uint32_t off =
                    SW128((uint32_t)((wn + p * 16 + b_row) * 128 + (kbase + b_k8) * 2));
                uint32_t t[4];
                ldsm_x4(t, st + ST1_BH + off);
                bh[2 * p][0] = t[0]; bh[2 * p][1] = t[1];
                bh[2 * p + 1][0] = t[2]; bh[2 * p + 1][1] = t[3];
            }
            #pragma unroll
            for (int mi = 0; mi < 4; mi++)
                #pragma unroll
                for (int ni = 0; ni < 4; ni++)
                    mma_f16(acc[mi][ni], ah[mi], bh[ni]);
        }
        __syncthreads();
    }
}

// --------------- merged conversion: x -> Xh  and  W -> Wth (transposed) ------
// grid: 1D, 256 threads. Blocks [0, XB): x-role. Blocks [XB, XB+3072): w-role.
#define XB (MTOT * DIM / (256 * 4))   // 8192

__global__ __launch_bounds__(256) void convert_inputs(
    const float* __restrict__ x,
    const float* __restrict__ Wq,
    const float* __restrict__ Wk,
    const float* __restrict__ Wv)
{
    const int tid = threadIdx.x;
    if (blockIdx.x < XB) {
        size_t i = ((size_t)blockIdx.x * 256 + tid) * 4;
        float4 v = *(const float4*)(x + i);
        *(uint32_t*)(Xh + i)     = pack_half2(__float2half_rn(v.x), __float2half_rn(v.y));
        *(uint32_t*)(Xh + i + 2) = pack_half2(__float2half_rn(v.z), __float2half_rn(v.w));
        return;
    }
    // w-role: wb in [0, 3072) -> (nb 32, kb 32, z 3)
    __shared__ float t[32][33];
    const int wb = blockIdx.x - XB;
    const int z  = wb >> 10;
    const int kb = (wb >> 5) & 31;
    const int nb = wb & 31;
    const float* W = (z == 0) ? Wq : ((z == 1) ? Wk : Wv);
    const int n0 = nb * 32, k0 = kb * 32;
    const int tx = tid & 31, ty = tid >> 5;
    #pragma unroll
    for (int r = ty; r < 32; r += 8)
        t[r][tx] = W[(size_t)(k0 + r) * DIM + n0 + tx];
    __syncthreads();
    __half* oh = Wth + (size_t)z * DIM * DIM;
    #pragma unroll
    for (int r = ty; r < 32; r += 8)
        oh[(size_t)(n0 + r) * DIM + k0 + tx] = __float2half_rn(t[tx][r]);
}

// ---------------- QK GEMM: Q and K projections (1-pass, 128x128) -------------
__global__ __launch_bounds__(256) void qk_gemm() {
    extern __shared__ char smg[];
    const int tid = threadIdx.x;
    const int wid = tid >> 5, lane = tid & 31;
    const int n0 = blockIdx.x * 128, m0 = blockIdx.y * 128, z = blockIdx.z;
    const int wm = (wid & 1) * 64, wn = (wid >> 1) * 32;

    float acc[4][4][4] = {};
    gemm_tile_1p(Xh + (size_t)m0 * DIM, DIM,
                 Wth + (size_t)z * DIM * DIM + (size_t)n0 * DIM, DIM,
                 DIM / 64, smg, acc);

    __half* D = (z == 0) ? Qh : Kh;
    #pragma unroll
    for (int mi = 0; mi < 4; mi++) {
        const int row0 = m0 + wm + mi * 16 + (lane >> 2);
        #pragma unroll
        for (int ni = 0; ni < 4; ni++) {
            const int col = n0 + wn + ni * 8 + (lane & 3) * 2;
            #pragma unroll
            for (int half = 0; half < 2; half++) {
                const size_t idx = (size_t)(row0 + half * 8) * DIM + col;
                *(uint32_t*)(D + idx) = pack_half2(
                    __float2half_rn(acc[mi][ni][half * 2 + 0]),
                    __float2half_rn(acc[mi][ni][half * 2 + 1]));
            }
        }
    }
}

// ---------------- fused launch: exp(S) (triangular) + V projection ----------
// grid (24, 16, 4): x<16 -> S-tile role (writes unnormalized exp as fp16);
//                   x>=16 -> V-projection role.
__global__ __launch_bounds__(256) void sv_gemm() {
    extern __shared__ char smg[];
    const int tid = threadIdx.x;
    const int wid = tid >> 5, lane = tid & 31;
    const int wm = (wid & 1) * 64, wn = (wid >> 1) * 32;

    if (blockIdx.x >= 16) {
        // ---- V projection role: vid in [0, 512) -> (m_blk 64, n_blk 8) ----
        const int vid = (blockIdx.x - 16) + 8 * (blockIdx.y + 16 * blockIdx.z);
        const int n0 = (vid & 7) * 128;
        const int m0 = (vid >> 3) * 128;

        float acc[4][4][4] = {};
        gemm_tile_1p(Xh + (size_t)m0 * DIM, DIM,
                     Wth + 2 * (size_t)DIM * DIM + (size_t)n0 * DIM, DIM,
                     DIM / 64, smg, acc);

        // transpose 32(d) x 64(s) warp tile via smem, write Vt[b][d][s]
        __syncthreads();
        __half* th = (__half*)smg + (size_t)wid * 32 * 66;
        #pragma unroll
        for (int mi = 0; mi < 4; mi++) {
            const int rl = mi * 16 + (lane >> 2);
            #pragma unroll
            for (int ni = 0; ni < 4; ni++) {
                const int cl = ni * 8 + (lane & 3) * 2;
                #pragma unroll
                for (int half = 0; half < 2; half++) {
                    const int r = rl + half * 8;
                    th[(cl + 0) * 66 + r] = __float2half_rn(acc[mi][ni][half * 2 + 0]);
                    th[(cl + 1) * 66 + r] = __float2half_rn(acc[mi][ni][half * 2 + 1]);
                }
            }
        }
        __syncwarp();
        const int b    = m0 >> 11;
        const int sloc = (m0 & (SEQ - 1)) + wm;
        __half* vth = Vth + (size_t)b * DIM * SEQ;
        #pragma unroll 4
        for (int c = 0; c < 32; c++) {
            *(uint32_t*)(vth + (size_t)(n0 + wn + c) * SEQ + sloc + lane * 2) =
                *(uint32_t*)(th + c * 66 + lane * 2);
        }
        return;
    }

    // ---- S role (triangular, heavy tiles first): Ph = exp(S*scale) masked ----
    const int bn = blockIdx.x;
    const int bm = gridDim.y - 1 - blockIdx.y;
    const int b  = blockIdx.z;
    if (bn > bm) return;                 // tile fully above diagonal
    const int m0 = bm * 128, n0 = bn * 128;

    const size_t boff = (size_t)b * SEQ * DIM;
    float acc[4][4][4] = {};
    gemm_tile_1p(Qh + boff + (size_t)m0 * DIM, DIM,
                 Kh + boff + (size_t)n0 * DIM, DIM,
                 DIM / 64, smg, acc);

    __half* P = Ph + (size_t)b * SEQ * SEQ;
    const float scale = 0.03125f;
    #pragma unroll
    for (int mi = 0; mi < 4; mi++) {
        const int row0 = m0 + wm + mi * 16 + (lane >> 2);
        #pragma unroll
        for (int ni = 0; ni < 4; ni++) {
            const int col = n0 + wn + ni * 8 + (lane & 3) * 2;
            #pragma unroll
            for (int half = 0; half < 2; half++) {
                const int row = row0 + half * 8;
                const float e0 = (col     <= row) ? __expf(acc[mi][ni][half * 2 + 0] * scale) : 0.0f;
                const float e1 = (col + 1 <= row) ? __expf(acc[mi][ni][half * 2 + 1] * scale) : 0.0f;
                *(uint32_t*)(P + (size_t)row * SEQ + col) =
                    pack_half2(__float2half_rn(e0), __float2half_rn(e1));
            }
        }
    }
}

// ---------------- rowsum: Rsum[b][q] = sum_k Ph[b][q][k] (fp32) --------------
__global__ __launch_bounds__(256) void rowsum_kernel() {
    __shared__ float red[8];
    const int q = blockIdx.x, b = blockIdx.y;
    const int rowpad2 = (((q >> 7) << 7) + 128) >> 1;   // half2 count
    const int tid = threadIdx.x, wid = tid >> 5, lane = tid & 31;

    const __half2* prow = (const __half2*)(Ph + ((size_t)b * SEQ + q) * SEQ);
    float sum = 0.0f;
    for (int i = tid; i < rowpad2; i += 256) {
        const float2 f = __half22float2(prow[i]);
        sum += f.x + f.y;
    }
    #pragma unroll
    for (int o = 16; o; o >>= 1) sum += __shfl_xor_sync(0xffffffffu, sum, o);
    if (lane == 0) red[wid] = sum;
    __syncthreads();
    if (tid == 0) {
        float s2 = red[0];
        #pragma unroll
        for (int i = 1; i < 8; i++) s2 += red[i];
        Rsum[b * SEQ + q] = s2;
    }
}

// ---------------- O GEMM: out = (Ph @ V) / Rsum (causal k-range) -------------
__global__ __launch_bounds__(256) void o_gemm(float* __restrict__ out) {
    extern __shared__ char smg[];
    const int tid = threadIdx.x;
    const int wid = tid >> 5, lane = tid & 31;
    const int bn = blockIdx.x;
    const int bm = gridDim.y - 1 - blockIdx.y;   // heavy rows first
    const int b  = blockIdx.z;
    const int m0 = bm * 128, n0 = bn * 128;
    const int wm = (wid & 1) * 64, wn = (wid >> 1) * 32;

    const size_t poff = (size_t)b * SEQ * SEQ;
    const size_t voff = (size_t)b * DIM * SEQ;
    float acc[4][4][4] = {};
    gemm_tile_1p(Ph + poff + (size_t)m0 * SEQ, SEQ,
                 Vth + voff + (size_t)n0 * SEQ, SEQ,
                 (m0 + 128) / 64, smg, acc);

    float* O = out + (size_t)b * SEQ * DIM;
    #pragma unroll
    for (int mi = 0; mi < 4; mi++) {
        const int row0 = m0 + wm + mi * 16 + (lane >> 2);
        const float inv0 = 1.0f / Rsum[b * SEQ + row0];
        const float inv1 = 1.0f / Rsum[b * SEQ + row0 + 8];
        #pragma unroll
        for (int ni = 0; ni < 4; ni++) {
            const int col = n0 + wn + ni * 8 + (lane & 3) * 2;
            *(float2*)(O + (size_t)row0 * DIM + col) =
                make_float2(acc[mi][ni][0] * inv0, acc[mi][ni][1] * inv0);
            *(float2*)(O + (size_t)(row0 + 8) * DIM + col) =
                make_float2(acc[mi][ni][2] * inv1, acc[mi][ni][3] * inv1);
        }
    }
}

// ---------------------------------------------------------------------------
extern "C" void kernel_launch(void* const* d_in, const int* in_sizes, int n_in,
                              void* d_out, int out_size)
{
    const float* x  = (const float*)d_in[0];
    const float* Wq = (const float*)d_in[1];
    const float* Wk = (const float*)d_in[2];
    const float* Wv = (const float*)d_in[3];
    float* out = (float*)d_out;

    cudaFuncSetAttribute(qk_gemm, cudaFuncAttributeMaxDynamicSharedMemorySize, GEMM1_SMEM);
    cudaFuncSetAttribute(sv_gemm, cudaFuncAttributeMaxDynamicSharedMemorySize, GEMM1_SMEM);
    cudaFuncSetAttribute(o_gemm,  cudaFuncAttributeMaxDynamicSharedMemorySize, GEMM1_SMEM);

    // fp32 -> fp16 (x and W in one launch)
    convert_inputs<<<XB + 3072, 256>>>(x, Wq, Wk, Wv);

    // Q + K projections (128x128 tiles, 3-stage pipeline)
    qk_gemm<<<dim3(DIM / 128, MTOT / 128, 2), 256, GEMM1_SMEM>>>();

    // Fused: exp(scores) (triangular, masked, unnormalized fp16) + V projection
    sv_gemm<<<dim3(24, 16, BATCH), 256, GEMM1_SMEM>>>();

    // Row sums of exp (softmax denominators)
    rowsum_kernel<<<dim3(SEQ, BATCH), 256>>>();

    // O = (Ph @ V) / Rsum (causal k-range)
    o_gemm<<<dim3(DIM / 128, SEQ / 128, BATCH), 256, GEMM1_SMEM>>>(out);
}

// round 17
// speedup vs baseline: 1.0100x; 1.0100x over previous
#include <cuda_runtime.h>
#include <cuda_fp16.h>
#include <cstdint>

#define BATCH 4
#define SEQ   2048
#define DIM   1024
#define MTOT  (BATCH*SEQ)

// ------------------------- device scratch (no allocs) -----------------------
__device__ __half Xh[MTOT*(size_t)DIM];
__device__ __half Wth[3*(size_t)DIM*DIM];    // [z][n][k], fp16(W) transposed
__device__ __half Qh[MTOT*(size_t)DIM];
__device__ __half Kh[MTOT*(size_t)DIM];
__device__ __half Vth[MTOT*(size_t)DIM];     // [b][d][s]
__device__ __half Ph [(size_t)BATCH*SEQ*SEQ];    // unnormalized exp(scores)
__device__ float  Rsum[MTOT];                    // per-row softmax denominators

// ------------------------------ helpers -------------------------------------
__device__ __forceinline__ uint32_t smem_to_u32(const void* p) {
    uint32_t a;
    asm("{ .reg .u64 t; cvta.to.shared.u64 t, %1; cvt.u32.u64 %0, t; }"
        : "=r"(a) : "l"(p));
    return a;
}
#define SW128(off) ((off) ^ (((off) >> 3) & 0x70))

__device__ __forceinline__ void ldsm_x4(uint32_t* r, uint32_t addr) {
    asm volatile("ldmatrix.sync.aligned.m8n8.x4.shared.b16 {%0,%1,%2,%3}, [%4];"
                 : "=r"(r[0]), "=r"(r[1]), "=r"(r[2]), "=r"(r[3]) : "r"(addr));
}
__device__ __forceinline__ void mma_f16(float* c, const uint32_t* a, const uint32_t* b) {
    asm volatile(
        "mma.sync.aligned.m16n8k16.row.col.f32.f16.f16.f32 "
        "{%0,%1,%2,%3}, {%4,%5,%6,%7}, {%8,%9}, {%0,%1,%2,%3};"
        : "+f"(c[0]), "+f"(c[1]), "+f"(c[2]), "+f"(c[3])
        : "r"(a[0]), "r"(a[1]), "r"(a[2]), "r"(a[3]), "r"(b[0]), "r"(b[1]));
}
__device__ __forceinline__ void cp16(uint32_t smem_dst, const void* gptr) {
    asm volatile("cp.async.cg.shared.global [%0], [%1], 16;"
                 :: "r"(smem_dst), "l"(gptr));
}
__device__ __forceinline__ uint32_t pack_half2(__half a, __half b) {
    __half2 h2 = __halves2half2(a, b);
    return *(uint32_t*)&h2;
}

// ----------------- 1-pass fp16 mainloop, 128m x 128n x 64k, 2 stages ---------
// 8 warps as 2(m) x 4(n): warp tile 64x32. acc[4][4][4].
// Stage (32 KB): Ah[16K] Bh[16K]; rows 128B, SW128. 2 stages = 64 KB -> 2 CTA/SM.
#define ST1_BH 16384
#define STAGE1 32768
#define GEMM1_SMEM (2*STAGE1)   // 65536

__device__ __forceinline__ void gemm_tile_1p(
    const __half* __restrict__ Ahp, size_t lda,
    const __half* __restrict__ Bhp, size_t ldb,
    int kIters, char* smem, float acc[4][4][4])
{
    const int tid = threadIdx.x;
    const int wid = tid >> 5, lane = tid & 31;
    const int wm = (wid & 1) * 64;      // warp m offset
    const int wn = (wid >> 1) * 32;     // warp n offset
    const uint32_t sbase = smem_to_u32(smem);

    const int r8 = tid >> 3, j8 = tid & 7;

    auto issue = [&](int c) {
        const int kc = c * 64;
        const uint32_t st = sbase + (c & 1) * STAGE1;
        #pragma unroll
        for (int i = 0; i < 4; i++) {
            const int r = r8 + i * 32;
            const uint32_t off = SW128((uint32_t)(r * 128 + j8 * 16));
            cp16(st + off,          Ahp + (size_t)r * lda + kc + j8 * 8);
            cp16(st + ST1_BH + off, Bhp + (size_t)r * ldb + kc + j8 * 8);
        }
        asm volatile("cp.async.commit_group;" ::: "memory");
    };

    const int a_row = (lane & 15);
    const int a_k8  = ((lane >> 4) & 1) * 8;
    const int b_row = (lane & 7) + ((lane >> 4) & 1) * 8;
    const int b_k8  = ((lane >> 3) & 1) * 8;

    issue(0);

    for (int c = 0; c < kIters; c++) {
        if (c + 1 < kIters) {
            issue(c + 1);
            asm volatile("cp.async.wait_group 1;" ::: "memory");
        } else {
            asm volatile("cp.async.wait_group 0;" ::: "memory");
        }
        __syncthreads();

        const uint32_t st = sbase + (c & 1) * STAGE1;
        #pragma unroll
        for (int ks = 0; ks < 4; ks++) {
            const int kbase = ks * 16;
            uint32_t ah[4][4];
            #pragma unroll
            for (int mi = 0; mi < 4; mi++) {
                const uint32_t off =
                    SW128((uint32_t)((wm + mi * 16 + a_row) * 128 + (kbase + a_k8) * 2));
                ldsm_x4(ah[mi], st + off);
            }
            uint32_t bh[4][2];
            #pragma unroll
            for (int p = 0; p < 2; p++) {
                const uint32_t off =
                    SW128((uint32_t)((wn + p * 16 + b_row) * 128 + (kbase + b_k8) * 2));
                uint32_t t[4];
                ldsm_x4(t, st + ST1_BH + off);
                bh[2 * p][0] = t[0]; bh[2 * p][1] = t[1];
                bh[2 * p + 1][0] = t[2]; bh[2 * p + 1][1] = t[3];
            }
            #pragma unroll
            for (int mi = 0; mi < 4; mi++)
                #pragma unroll
                for (int ni = 0; ni < 4; ni++)
                    mma_f16(acc[mi][ni], ah[mi], bh[ni]);
        }
        __syncthreads();
    }
}

// --------------- merged conversion: x -> Xh  and  W -> Wth (transposed) ------
#define XB (MTOT * DIM / (256 * 4))   // 8192

__global__ __launch_bounds__(256) void convert_inputs(
    const float* __restrict__ x,
    const float* __restrict__ Wq,
    const float* __restrict__ Wk,
    const float* __restrict__ Wv)
{
    const int tid = threadIdx.x;
    if (blockIdx.x < XB) {
        size_t i = ((size_t)blockIdx.x * 256 + tid) * 4;
        float4 v = *(const float4*)(x + i);
        *(uint32_t*)(Xh + i)     = pack_half2(__float2half_rn(v.x), __float2half_rn(v.y));
        *(uint32_t*)(Xh + i + 2) = pack_half2(__float2half_rn(v.z), __float2half_rn(v.w));
        return;
    }
    __shared__ float t[32][33];
    const int wb = blockIdx.x - XB;
    const int z  = wb >> 10;
    const int kb = (wb >> 5) & 31;
    const int nb = wb & 31;
    const float* W = (z == 0) ? Wq : ((z == 1) ? Wk : Wv);
    const int n0 = nb * 32, k0 = kb * 32;
    const int tx = tid & 31, ty = tid >> 5;
    #pragma unroll
    for (int r = ty; r < 32; r += 8)
        t[r][tx] = W[(size_t)(k0 + r) * DIM + n0 + tx];
    __syncthreads();
    __half* oh = Wth + (size_t)z * DIM * DIM;
    #pragma unroll
    for (int r = ty; r < 32; r += 8)
        oh[(size_t)(n0 + r) * DIM + k0 + tx] = __float2half_rn(t[tx][r]);
}

// ---------------- QKV GEMM: Q, K ([s][d]) and V (transposed [d][s]) ----------
__global__ __launch_bounds__(256) void qkv_gemm() {
    extern __shared__ char smg[];
    const int tid = threadIdx.x;
    const int wid = tid >> 5, lane = tid & 31;
    const int n0 = blockIdx.x * 128, m0 = blockIdx.y * 128, z = blockIdx.z;
    const int wm = (wid & 1) * 64, wn = (wid >> 1) * 32;

    float acc[4][4][4] = {};
    gemm_tile_1p(Xh + (size_t)m0 * DIM, DIM,
                 Wth + (size_t)z * DIM * DIM + (size_t)n0 * DIM, DIM,
                 DIM / 64, smg, acc);

    if (z == 2) {
        // V epilogue: transpose 32(d) x 64(s) warp tile via smem -> Vt[b][d][s]
        __syncthreads();
        __half* th = (__half*)smg + (size_t)wid * 32 * 66;
        #pragma unroll
        for (int mi = 0; mi < 4; mi++) {
            const int rl = mi * 16 + (lane >> 2);
            #pragma unroll
            for (int ni = 0; ni < 4; ni++) {
                const int cl = ni * 8 + (lane & 3) * 2;
                #pragma unroll
                for (int half = 0; half < 2; half++) {
                    const int r = rl + half * 8;
                    th[(cl + 0) * 66 + r] = __float2half_rn(acc[mi][ni][half * 2 + 0]);
                    th[(cl + 1) * 66 + r] = __float2half_rn(acc[mi][ni][half * 2 + 1]);
                }
            }
        }
        __syncwarp();
        const int b    = m0 >> 11;
        const int sloc = (m0 & (SEQ - 1)) + wm;
        __half* vth = Vth + (size_t)b * DIM * SEQ;
        #pragma unroll 4
        for (int c = 0; c < 32; c++) {
            *(uint32_t*)(vth + (size_t)(n0 + wn + c) * SEQ + sloc + lane * 2) =
                *(uint32_t*)(th + c * 66 + lane * 2);
        }
        return;
    }

    __half* D = (z == 0) ? Qh : Kh;
    #pragma unroll
    for (int mi = 0; mi < 4; mi++) {
        const int row0 = m0 + wm + mi * 16 + (lane >> 2);
        #pragma unroll
        for (int ni = 0; ni < 4; ni++) {
            const int col = n0 + wn + ni * 8 + (lane & 3) * 2;
            #pragma unroll
            for (int half = 0; half < 2; half++) {
                const size_t idx = (size_t)(row0 + half * 8) * DIM + col;
                *(uint32_t*)(D + idx) = pack_half2(
                    __float2half_rn(acc[mi][ni][half * 2 + 0]),
                    __float2half_rn(acc[mi][ni][half * 2 + 1]));
            }
        }
    }
}

// ---------------- S GEMM: Ph = exp(Q@K^T * scale) masked (triangular) --------
__global__ __launch_bounds__(256) void s_gemm() {
    extern __shared__ char smg[];
    const int tid = threadIdx.x;
    const int wid = tid >> 5, lane = tid & 31;
    const int wm = (wid & 1) * 64, wn = (wid >> 1) * 32;

    const int bn = blockIdx.x;
    const int bm = gridDim.y - 1 - blockIdx.y;   // heavy tiles first
    const int b  = blockIdx.z;
    if (bn > bm) return;                         // tile fully above diagonal
    const int m0 = bm * 128, n0 = bn * 128;

    const size_t boff = (size_t)b * SEQ * DIM;
    float acc[4][4][4] = {};
    gemm_tile_1p(Qh + boff + (size_t)m0 * DIM, DIM,
                 Kh + boff + (size_t)n0 * DIM, DIM,
                 DIM / 64, smg, acc);

    __half* P = Ph + (size_t)b * SEQ * SEQ;
    const float scale = 0.03125f;
    #pragma unroll
    for (int mi = 0; mi < 4; mi++) {
        const int row0 = m0 + wm + mi * 16 + (lane >> 2);
        #pragma unroll
        for (int ni = 0; ni < 4; ni++) {
            const int col = n0 + wn + ni * 8 + (lane & 3) * 2;
            #pragma unroll
            for (int half = 0; half < 2; half++) {
                const int row = row0 + half * 8;
                const float e0 = (col     <= row) ? __expf(acc[mi][ni][half * 2 + 0] * scale) : 0.0f;
                const float e1 = (col + 1 <= row) ? __expf(acc[mi][ni][half * 2 + 1] * scale) : 0.0f;
                *(uint32_t*)(P + (size_t)row * SEQ + col) =
                    pack_half2(__float2half_rn(e0), __float2half_rn(e1));
            }
        }
    }
}

// ---------------- rowsum: warp per row, no block barriers --------------------
__global__ __launch_bounds__(256) void rowsum_kernel() {
    const int wid = threadIdx.x >> 5, lane = threadIdx.x & 31;
    const int q = blockIdx.x * 8 + wid;
    const int b = blockIdx.y;
    const int rowpad2 = (((q >> 7) << 7) + 128) >> 1;   // half2 count

    const __half2* prow = (const __half2*)(Ph + ((size_t)b * SEQ + q) * SEQ);
    float sum = 0.0f;
    for (int i = lane; i < rowpad2; i += 32) {
        const float2 f = __half22float2(prow[i]);
        sum += f.x + f.y;
    }
    #pragma unroll
    for (int o = 16; o; o >>= 1) sum += __shfl_xor_sync(0xffffffffu, sum, o);
    if (lane == 0) Rsum[b * SEQ + q] = sum;
}

// ---------------- O GEMM: out = (Ph @ V) / Rsum (causal k-range) -------------
__global__ __launch_bounds__(256) void o_gemm(float* __restrict__ out) {
    extern __shared__ char smg[];
    const int tid = threadIdx.x;
    const int wid = tid >> 5, lane = tid & 31;
    const int bn = blockIdx.x;
    const int bm = gridDim.y - 1 - blockIdx.y;   // heavy rows first
    const int b  = blockIdx.z;
    const int m0 = bm * 128, n0 = bn * 128;
    const int wm = (wid & 1) * 64, wn = (wid >> 1) * 32;

    const size_t poff = (size_t)b * SEQ * SEQ;
    const size_t voff = (size_t)b * DIM * SEQ;
    float acc[4][4][4] = {};
    gemm_tile_1p(Ph + poff + (size_t)m0 * SEQ, SEQ,
                 Vth + voff + (size_t)n0 * SEQ, SEQ,
                 (m0 + 128) / 64, smg, acc);

    float* O = out + (size_t)b * SEQ * DIM;
    #pragma unroll
    for (int mi = 0; mi < 4; mi++) {
        const int row0 = m0 + wm + mi * 16 + (lane >> 2);
        const float inv0 = 1.0f / Rsum[b * SEQ + row0];
        const float inv1 = 1.0f / Rsum[b * SEQ + row0 + 8];
        #pragma unroll
        for (int ni = 0; ni < 4; ni++) {
            const int col = n0 + wn + ni * 8 + (lane & 3) * 2;
            *(float2*)(O + (size_t)row0 * DIM + col) =
                make_float2(acc[mi][ni][0] * inv0, acc[mi][ni][1] * inv0);
            *(float2*)(O + (size_t)(row0 + 8) * DIM + col) =
                make_float2(acc[mi][ni][2] * inv1, acc[mi][ni][3] * inv1);
        }
    }
}

// ---------------------------------------------------------------------------
extern "C" void kernel_launch(void* const* d_in, const int* in_sizes, int n_in,
                              void* d_out, int out_size)
{
    const float* x  = (const float*)d_in[0];
    const float* Wq = (const float*)d_in[1];
    const float* Wk = (const float*)d_in[2];
    const float* Wv = (const float*)d_in[3];
    float* out = (float*)d_out;

    cudaFuncSetAttribute(qkv_gemm, cudaFuncAttributeMaxDynamicSharedMemorySize, GEMM1_SMEM);
    cudaFuncSetAttribute(s_gemm,   cudaFuncAttributeMaxDynamicSharedMemorySize, GEMM1_SMEM);
    cudaFuncSetAttribute(o_gemm,   cudaFuncAttributeMaxDynamicSharedMemorySize, GEMM1_SMEM);

    // fp32 -> fp16 (x and W in one launch)
    convert_inputs<<<XB + 3072, 256>>>(x, Wq, Wk, Wv);

    // Q, K, V projections in one launch (V written transposed)
    qkv_gemm<<<dim3(DIM / 128, MTOT / 128, 3), 256, GEMM1_SMEM>>>();

    // exp(scores) (triangular, masked, unnormalized fp16)
    s_gemm<<<dim3(SEQ / 128, SEQ / 128, BATCH), 256, GEMM1_SMEM>>>();

    // Row sums of exp (softmax denominators), warp-per-row
    rowsum_kernel<<<dim3(SEQ / 8, BATCH), 256>>>();

    // O = (Ph @ V) / Rsum (causal k-range)
    o_gemm<<<dim3(DIM / 128, SEQ / 128, BATCH), 256, GEMM1_SMEM>>>(out);
}